// round 1
// baseline (speedup 1.0000x reference)
#include <cuda_runtime.h>
#include <cstdint>

// ExpertAttention: B=128, S=128, H=768, E=2, 12 heads x 64
// Strategy: compute routing first, then run ONLY the assigned expert per batch
// row (2x less work than the reference's dense-both-experts approach).
//
// Inputs (metadata order):
//  0 hidden_states  [128,128,768] f32
//  1 attention_mask [128,128]     f32
//  2 routing_states [128,128,768] f32
//  3 centers        [2,768]       f32
//  4 Wq [2,768,768]  5 bq [2,768]
//  6 Wk [2,768,768]  7 bk [2,768]
//  8 Wv [2,768,768]  9 bv [2,768]
// 10 Wo [2,768,768] 11 bo [2,768]
// out [128,128,768] f32

#define BB   128
#define SS   128
#define HH   768
#define NH   12
#define HD   64

typedef unsigned long long u64;

// ------------------------- scratch (static device mem) -------------------------
__device__ int   g_assign[BB];
__device__ float g_q[(size_t)BB * SS * HH];
__device__ float g_k[(size_t)BB * SS * HH];
__device__ float g_v[(size_t)BB * SS * HH];
__device__ float g_ctx[(size_t)BB * SS * HH];

// ------------------------- f32x2 helpers -------------------------
__device__ __forceinline__ u64 pack2(float lo, float hi) {
    u64 r;
    asm("mov.b64 %0, {%1, %2};" : "=l"(r) : "f"(lo), "f"(hi));
    return r;
}
__device__ __forceinline__ u64 fma2(u64 a, u64 b, u64 c) {
    u64 d;
    asm("fma.rn.f32x2 %0, %1, %2, %3;" : "=l"(d) : "l"(a), "l"(b), "l"(c));
    return d;
}
__device__ __forceinline__ void unpack2(u64 v, float& lo, float& hi) {
    asm("mov.b64 {%0, %1}, %2;" : "=f"(lo), "=f"(hi) : "l"(v));
}

// ------------------------- routing -------------------------
// One block per batch row: mean-pool routing_states over S, L2 distance to the
// 2 centers, argmin (first-min tie break like jnp.argmin -> strict <).
__global__ void routing_kernel(const float* __restrict__ rs,
                               const float* __restrict__ centers) {
    const int b   = blockIdx.x;
    const int tid = threadIdx.x;  // 256

    float d0 = 0.f, d1 = 0.f;
    for (int h = tid; h < HH; h += 256) {
        const float* p = rs + (size_t)b * SS * HH + h;
        float s = 0.f;
        #pragma unroll 8
        for (int t = 0; t < SS; t++) s += p[(size_t)t * HH];
        float m  = s * (1.0f / 128.0f);
        float e0 = m - centers[h];
        float e1 = m - centers[HH + h];
        d0 += e0 * e0;
        d1 += e1 * e1;
    }
    __shared__ float s0[256], s1[256];
    s0[tid] = d0; s1[tid] = d1;
    __syncthreads();
    for (int w = 128; w > 0; w >>= 1) {
        if (tid < w) { s0[tid] += s0[tid + w]; s1[tid] += s1[tid + w]; }
        __syncthreads();
    }
    if (tid == 0) g_assign[b] = (s1[0] < s0[0]) ? 1 : 0;
}

// ------------------------- expert GEMM -------------------------
// Y[b, s, n] = sum_h X[b, s, h] * W[assign[b], h, n] + bias[assign[b], n]
// Block tile: 128 (all S rows) x 64 cols, BK=16. 256 threads, 8x4 micro-tile,
// f32x2 packed accumulators (2 MACs per FMA issue).
// Grid: (12 n-tiles, 128 b)
__global__ __launch_bounds__(256, 2)
void gemm_expert(const float* __restrict__ X,
                 const float* __restrict__ Wall,
                 const float* __restrict__ ball,
                 float* __restrict__ Y) {
    const int b  = blockIdx.y;
    const int n0 = blockIdx.x * 64;
    const int e  = g_assign[b];

    const float* __restrict__ Wp = Wall + (size_t)e * HH * HH;
    const float* __restrict__ bp = ball + e * HH;
    const float* __restrict__ A  = X + (size_t)b * SS * HH;
    float* __restrict__       C  = Y + (size_t)b * SS * HH;

    __shared__ u64   As2[16][128];  // [k][m], each element = (a, a) packed pair
    __shared__ float Bs[16][64];    // [k][n]

    const int tid = threadIdx.x;
    const int tx  = tid & 15;   // n: cols tx*4 .. tx*4+3
    const int ty  = tid >> 4;   // m: rows ty*8 .. ty*8+7

    const int a_row0 = tid >> 2;         // 0..63 (second pass: +64)
    const int a_c    = (tid & 3) * 4;    // 0,4,8,12
    const int b_row  = tid >> 4;         // 0..15
    const int b_c    = (tid & 15) * 4;   // 0..60

    u64 acc[8][2];
    #pragma unroll
    for (int i = 0; i < 8; i++) { acc[i][0] = 0ull; acc[i][1] = 0ull; }

    for (int k0 = 0; k0 < HH; k0 += 16) {
        #pragma unroll
        for (int t = 0; t < 2; t++) {
            int row = a_row0 + t * 64;
            float4 v = *(const float4*)(A + (size_t)row * HH + k0 + a_c);
            As2[a_c + 0][row] = pack2(v.x, v.x);
            As2[a_c + 1][row] = pack2(v.y, v.y);
            As2[a_c + 2][row] = pack2(v.z, v.z);
            As2[a_c + 3][row] = pack2(v.w, v.w);
        }
        *(float4*)&Bs[b_row][b_c] =
            *(const float4*)(Wp + (size_t)(k0 + b_row) * HH + n0 + b_c);
        __syncthreads();

        #pragma unroll
        for (int k = 0; k < 16; k++) {
            ulonglong2 a01 = *(const ulonglong2*)&As2[k][ty * 8 + 0];
            ulonglong2 a23 = *(const ulonglong2*)&As2[k][ty * 8 + 2];
            ulonglong2 a45 = *(const ulonglong2*)&As2[k][ty * 8 + 4];
            ulonglong2 a67 = *(const ulonglong2*)&As2[k][ty * 8 + 6];
            ulonglong2 bb  = *(const ulonglong2*)&Bs[k][tx * 4];
            u64 a[8] = {a01.x, a01.y, a23.x, a23.y, a45.x, a45.y, a67.x, a67.y};
            #pragma unroll
            for (int i = 0; i < 8; i++) {
                acc[i][0] = fma2(a[i], bb.x, acc[i][0]);
                acc[i][1] = fma2(a[i], bb.y, acc[i][1]);
            }
        }
        __syncthreads();
    }

    float4 bv = *(const float4*)(bp + n0 + tx * 4);
    #pragma unroll
    for (int i = 0; i < 8; i++) {
        float4 o;
        unpack2(acc[i][0], o.x, o.y);
        unpack2(acc[i][1], o.z, o.w);
        o.x += bv.x; o.y += bv.y; o.z += bv.z; o.w += bv.w;
        *(float4*)(C + (size_t)(ty * 8 + i) * HH + n0 + tx * 4) = o;
    }
}

// ------------------------- attention -------------------------
// One block per (head, batch). Full 128x128 score matrix in SMEM.
// SMEM: Qs[128][64] (reused for V), Kt[64][128] (K transposed), P[128][132], em[128]
#define P_STR 132
#define ATTN_SMEM_FLOATS (128 * 64 + 64 * 128 + 128 * P_STR + 128)
#define ATTN_SMEM_BYTES  (ATTN_SMEM_FLOATS * 4)

__global__ __launch_bounds__(256)
void attn_kernel(const float* __restrict__ mask) {
    extern __shared__ float sm[];
    float* Qs = sm;                          // [128][64], later V
    float* Kt = sm + 128 * 64;               // [64][128]
    float* P  = Kt + 64 * 128;               // [128][P_STR]
    float* em = P + 128 * P_STR;             // [128]

    const int h0  = blockIdx.x;
    const int b   = blockIdx.y;
    const int tid = threadIdx.x;  // 256

    if (tid < 128) em[tid] = (1.0f - mask[b * SS + tid]) * -10000.0f;

    const size_t base = (size_t)b * SS * HH + h0 * HD;
    const float* qb = g_q + base;
    const float* kb = g_k + base;
    const float* vb = g_v + base;

    // load Q [128][64] row-major, K transposed to Kt[d][t]
    #pragma unroll
    for (int t = 0; t < 8; t++) {
        int idx = tid + t * 256;              // 0..2047 float4s
        int row = idx >> 4;                   // 0..127
        int c4  = (idx & 15) * 4;             // 0..60
        float4 q4 = *(const float4*)(qb + (size_t)row * HH + c4);
        *(float4*)&Qs[row * 64 + c4] = q4;
        float4 k4 = *(const float4*)(kb + (size_t)row * HH + c4);
        Kt[(c4 + 0) * 128 + row] = k4.x;
        Kt[(c4 + 1) * 128 + row] = k4.y;
        Kt[(c4 + 2) * 128 + row] = k4.z;
        Kt[(c4 + 3) * 128 + row] = k4.w;
    }
    __syncthreads();

    const int tx = tid & 15;   // key cols tx*8..+7
    const int ty = tid >> 4;   // query rows ty*8..+7

    // scores S = Q K^T
    float acc[8][8];
    #pragma unroll
    for (int i = 0; i < 8; i++)
        #pragma unroll
        for (int j = 0; j < 8; j++) acc[i][j] = 0.f;

    #pragma unroll 4
    for (int d = 0; d < HD; d++) {
        float q[8], kk[8];
        #pragma unroll
        for (int i = 0; i < 8; i++) q[i] = Qs[(ty * 8 + i) * 64 + d];
        #pragma unroll
        for (int j = 0; j < 8; j++) kk[j] = Kt[d * 128 + tx * 8 + j];
        #pragma unroll
        for (int i = 0; i < 8; i++)
            #pragma unroll
            for (int j = 0; j < 8; j++) acc[i][j] += q[i] * kk[j];
    }

    const float scale = 0.125f;  // 1/sqrt(64)
    #pragma unroll
    for (int i = 0; i < 8; i++) {
        int r = ty * 8 + i;
        #pragma unroll
        for (int jj = 0; jj < 8; jj += 4) {
            int c = tx * 8 + jj;
            float4 o;
            o.x = acc[i][jj + 0] * scale + em[c + 0];
            o.y = acc[i][jj + 1] * scale + em[c + 1];
            o.z = acc[i][jj + 2] * scale + em[c + 2];
            o.w = acc[i][jj + 3] * scale + em[c + 3];
            *(float4*)&P[r * P_STR + c] = o;
        }
    }
    __syncthreads();

    // softmax: 2 threads per row
    {
        int row = tid >> 1;
        int off = (tid & 1) * 64;
        float* pr = &P[row * P_STR + off];
        float mx = -1e30f;
        #pragma unroll 8
        for (int j = 0; j < 64; j++) mx = fmaxf(mx, pr[j]);
        mx = fmaxf(mx, __shfl_xor_sync(0xffffffffu, mx, 1));
        float sum = 0.f;
        #pragma unroll 8
        for (int j = 0; j < 64; j++) {
            float ev = __expf(pr[j] - mx);
            pr[j] = ev;
            sum += ev;
        }
        sum += __shfl_xor_sync(0xffffffffu, sum, 1);
        float inv = 1.0f / sum;
        #pragma unroll 8
        for (int j = 0; j < 64; j++) pr[j] *= inv;
    }
    __syncthreads();

    // load V into Qs buffer
    #pragma unroll
    for (int t = 0; t < 8; t++) {
        int idx = tid + t * 256;
        int row = idx >> 4;
        int c4  = (idx & 15) * 4;
        *(float4*)&Qs[row * 64 + c4] = *(const float4*)(vb + (size_t)row * HH + c4);
    }
    __syncthreads();

    // ctx = P @ V  (output rows ty*8..+7, cols tx*4..+3)
    float acc2[8][4] = {};
    #pragma unroll 2
    for (int t0 = 0; t0 < 128; t0 += 4) {
        float pp[8][4];
        #pragma unroll
        for (int i = 0; i < 8; i++) {
            float4 pv = *(const float4*)&P[(ty * 8 + i) * P_STR + t0];
            pp[i][0] = pv.x; pp[i][1] = pv.y; pp[i][2] = pv.z; pp[i][3] = pv.w;
        }
        #pragma unroll
        for (int u = 0; u < 4; u++) {
            float4 vv = *(const float4*)&Qs[(t0 + u) * 64 + tx * 4];
            #pragma unroll
            for (int i = 0; i < 8; i++) {
                acc2[i][0] += pp[i][u] * vv.x;
                acc2[i][1] += pp[i][u] * vv.y;
                acc2[i][2] += pp[i][u] * vv.z;
                acc2[i][3] += pp[i][u] * vv.w;
            }
        }
    }

    float* cb = g_ctx + base;
    #pragma unroll
    for (int i = 0; i < 8; i++) {
        float4 o = make_float4(acc2[i][0], acc2[i][1], acc2[i][2], acc2[i][3]);
        *(float4*)(cb + (size_t)(ty * 8 + i) * HH + tx * 4) = o;
    }
}

// ------------------------- launch -------------------------
extern "C" void kernel_launch(void* const* d_in, const int* in_sizes, int n_in,
                              void* d_out, int out_size) {
    const float* hidden  = (const float*)d_in[0];
    const float* mask    = (const float*)d_in[1];
    const float* rstates = (const float*)d_in[2];
    const float* centers = (const float*)d_in[3];
    const float* Wq = (const float*)d_in[4];
    const float* bq = (const float*)d_in[5];
    const float* Wk = (const float*)d_in[6];
    const float* bk = (const float*)d_in[7];
    const float* Wv = (const float*)d_in[8];
    const float* bv = (const float*)d_in[9];
    const float* Wo = (const float*)d_in[10];
    const float* bo = (const float*)d_in[11];
    float* out = (float*)d_out;

    void *pq, *pk, *pv, *pc;
    cudaGetSymbolAddress(&pq, g_q);
    cudaGetSymbolAddress(&pk, g_k);
    cudaGetSymbolAddress(&pv, g_v);
    cudaGetSymbolAddress(&pc, g_ctx);

    cudaFuncSetAttribute(attn_kernel,
                         cudaFuncAttributeMaxDynamicSharedMemorySize,
                         ATTN_SMEM_BYTES);

    routing_kernel<<<BB, 256>>>(rstates, centers);

    dim3 gg(HH / 64, BB);  // (12, 128)
    gemm_expert<<<gg, 256>>>(hidden, Wq, bq, (float*)pq);
    gemm_expert<<<gg, 256>>>(hidden, Wk, bk, (float*)pk);
    gemm_expert<<<gg, 256>>>(hidden, Wv, bv, (float*)pv);

    attn_kernel<<<dim3(NH, BB), 256, ATTN_SMEM_BYTES>>>(mask);

    gemm_expert<<<gg, 256>>>((const float*)pc, Wo, bo, out);
}

// round 5
// speedup vs baseline: 2.8683x; 2.8683x over previous
#include <cuda_runtime.h>
#include <cuda_bf16.h>
#include <cstdint>

// ExpertAttention: B=128, S=128, H=768, E=2, 12 heads x 64
// R5 (= R4 resubmit): mma.sync.m16n8k16 bf16 tensor cores (3-term split for
// fp32 accuracy) + cp.async + ldmatrix. Toolchain targets plain sm_100, so no
// tcgen05; this is the fastest legal tensor-core path.

#define BB   128
#define SS   128
#define HH   768
#define NH   12
#define HD   64

typedef __nv_bfloat16 bf16;

// ------------------------- scratch (static device mem) -------------------------
__device__ int   g_assign[BB];
__device__ __align__(16) float g_q[(size_t)BB * SS * HH];
__device__ __align__(16) float g_k[(size_t)BB * SS * HH];
__device__ __align__(16) float g_v[(size_t)BB * SS * HH];
__device__ __align__(16) float g_ctx[(size_t)BB * SS * HH];
__device__ __align__(16) bf16  g_xhi[(size_t)BB * SS * HH];
__device__ __align__(16) bf16  g_xlo[(size_t)BB * SS * HH];
// transposed weights [mat][e][n][h], mat in {q,k,v,o}
__device__ __align__(16) bf16  g_whi[(size_t)4 * 2 * HH * HH];
__device__ __align__(16) bf16  g_wlo[(size_t)4 * 2 * HH * HH];

// ------------------------- helpers -------------------------
__device__ __forceinline__ uint32_t smem_u32(const void* p) {
    uint32_t a;
    asm("{ .reg .u64 t; cvta.to.shared.u64 t, %1; cvt.u32.u64 %0, t; }" : "=r"(a) : "l"(p));
    return a;
}

#define CP16(dst, src) \
    asm volatile("cp.async.cg.shared.global [%0], [%1], 16;" :: "r"(dst), "l"(src))
#define CP_COMMIT() asm volatile("cp.async.commit_group;" ::: "memory")
#define CP_WAIT1()  asm volatile("cp.async.wait_group 1;" ::: "memory")
#define CP_WAIT0()  asm volatile("cp.async.wait_group 0;" ::: "memory")

struct Frag4 { uint32_t r[4]; };

__device__ __forceinline__ Frag4 ldsm4(uint32_t addr) {
    Frag4 f;
    asm volatile("ldmatrix.sync.aligned.m8n8.x4.shared.b16 {%0,%1,%2,%3}, [%4];"
                 : "=r"(f.r[0]), "=r"(f.r[1]), "=r"(f.r[2]), "=r"(f.r[3]) : "r"(addr));
    return f;
}

__device__ __forceinline__ void mma16816(float* d, const Frag4& a, uint32_t b0, uint32_t b1) {
    asm volatile(
        "mma.sync.aligned.m16n8k16.row.col.f32.bf16.bf16.f32 "
        "{%0,%1,%2,%3}, {%4,%5,%6,%7}, {%8,%9}, {%0,%1,%2,%3};"
        : "+f"(d[0]), "+f"(d[1]), "+f"(d[2]), "+f"(d[3])
        : "r"(a.r[0]), "r"(a.r[1]), "r"(a.r[2]), "r"(a.r[3]), "r"(b0), "r"(b1));
}

// ------------------------- routing -------------------------
__global__ void routing_kernel(const float* __restrict__ rs,
                               const float* __restrict__ centers) {
    const int b   = blockIdx.x;
    const int tid = threadIdx.x;  // 256

    float d0 = 0.f, d1 = 0.f;
    for (int h = tid; h < HH; h += 256) {
        const float* p = rs + (size_t)b * SS * HH + h;
        float s = 0.f;
        #pragma unroll 8
        for (int t = 0; t < SS; t++) s += p[(size_t)t * HH];
        float m  = s * (1.0f / 128.0f);
        float e0 = m - centers[h];
        float e1 = m - centers[HH + h];
        d0 += e0 * e0;
        d1 += e1 * e1;
    }
    __shared__ float s0[256], s1[256];
    s0[tid] = d0; s1[tid] = d1;
    __syncthreads();
    for (int w = 128; w > 0; w >>= 1) {
        if (tid < w) { s0[tid] += s0[tid + w]; s1[tid] += s1[tid + w]; }
        __syncthreads();
    }
    if (tid == 0) g_assign[b] = (s1[0] < s0[0]) ? 1 : 0;
}

// ------------------------- conversions -------------------------
__global__ void conv_act(const float* __restrict__ x, bf16* __restrict__ hi,
                         bf16* __restrict__ lo, int n4) {
    int i = blockIdx.x * blockDim.x + threadIdx.x;
    int stride = gridDim.x * blockDim.x;
    for (; i < n4; i += stride) {
        float4 v = ((const float4*)x)[i];
        bf16 h0 = __float2bfloat16(v.x);
        bf16 h1 = __float2bfloat16(v.y);
        bf16 h2 = __float2bfloat16(v.z);
        bf16 h3 = __float2bfloat16(v.w);
        bf16 l0 = __float2bfloat16(v.x - __bfloat162float(h0));
        bf16 l1 = __float2bfloat16(v.y - __bfloat162float(h1));
        bf16 l2 = __float2bfloat16(v.z - __bfloat162float(h2));
        bf16 l3 = __float2bfloat16(v.w - __bfloat162float(h3));
        __nv_bfloat162* ph = (__nv_bfloat162*)hi;
        __nv_bfloat162* pl = (__nv_bfloat162*)lo;
        ph[2 * i]     = __nv_bfloat162(h0, h1);
        ph[2 * i + 1] = __nv_bfloat162(h2, h3);
        pl[2 * i]     = __nv_bfloat162(l0, l1);
        pl[2 * i + 1] = __nv_bfloat162(l2, l3);
    }
}

// W[e][h][n] f32 -> hi/lo[e][n][h] bf16 (transpose + split). grid (24,24,2), block (32,8)
__global__ void conv_w(const float* __restrict__ W, bf16* __restrict__ hi,
                       bf16* __restrict__ lo) {
    __shared__ float t[32][33];
    const int e = blockIdx.z;
    const float* Wp = W + (size_t)e * HH * HH;
    const int h0 = blockIdx.x * 32, n0 = blockIdx.y * 32;
    for (int r = threadIdx.y; r < 32; r += 8)
        t[r][threadIdx.x] = Wp[(size_t)(h0 + r) * HH + n0 + threadIdx.x];
    __syncthreads();
    const size_t ob = (size_t)e * HH * HH;
    for (int r = threadIdx.y; r < 32; r += 8) {
        float v = t[threadIdx.x][r];  // = W[h0+tx][n0+r]
        bf16 h = __float2bfloat16(v);
        bf16 l = __float2bfloat16(v - __bfloat162float(h));
        size_t o = ob + (size_t)(n0 + r) * HH + h0 + threadIdx.x;
        hi[o] = h;
        lo[o] = l;
    }
}

// ------------------------- mma.sync GEMM -------------------------
// Y[b,s,n] = sum_h X[b,s,h]*W[e,h,n] + bias[e,n], bf16 3-term split
// (AhBh + AhBl + AlBh; dropped AlBl term ~2^-18 relative).
// Block 128x128x32, 256 thr / 8 warps (2m x 4n), warp tile 64x32.
// SMEM stage (40960B): Ahi@0, Alo@10240, Bhi@20480, Blo@30720; rows padded
// to 80B (40 bf16) -> conflict-free ldmatrix. Double buffered via cp.async.
#define STAGE_BYTES 40960
#define GEMM_SMEM   (2 * STAGE_BYTES)
#define ROWB        80

__global__ __launch_bounds__(256, 2)
void gemm_mma(const bf16* __restrict__ Xhi, const bf16* __restrict__ Xlo,
              const bf16* __restrict__ Whi, const bf16* __restrict__ Wlo,
              const float* __restrict__ bq, const float* __restrict__ bk,
              const float* __restrict__ bv,
              float* __restrict__ Y0, float* __restrict__ Y1, float* __restrict__ Y2) {
    extern __shared__ char smem[];
    const int tid  = threadIdx.x;
    const int lane = tid & 31;
    const int wid  = tid >> 5;
    const int wm   = wid & 1;   // 0..1 -> m offset wm*64
    const int wn   = wid >> 1;  // 0..3 -> n offset wn*32

    const int n0  = blockIdx.x * 128;
    const int b   = blockIdx.y;
    const int mat = blockIdx.z;
    const int e   = g_assign[b];

    const float* __restrict__ bias = ((mat == 0) ? bq : (mat == 1) ? bk : bv) + e * HH;
    float* __restrict__ Y = (mat == 0) ? Y0 : (mat == 1) ? Y1 : Y2;

    const size_t woff = ((size_t)mat * 2 + e) * HH * HH;
    const bf16* __restrict__ Xh = Xhi + (size_t)b * SS * HH;
    const bf16* __restrict__ Xl = Xlo + (size_t)b * SS * HH;
    const bf16* __restrict__ Wh = Whi + woff;
    const bf16* __restrict__ Wl = Wlo + woff;

    const uint32_t sbase = smem_u32(smem);

    // per-thread load mapping: 2 vectors per matrix per stage
    const int v0row = tid >> 2;         // 0..63
    const int v0c8  = tid & 3;          // 0..3 (16B chunks of 32 bf16)

    // ldmatrix lane geometry (x4 lane-group -> fragment order, see derivation)
    const int a_r  = (lane & 7) + ((lane >> 3) & 1) * 8;  // A: row within 16
    const int a_kc = (lane >> 4) * 8;                     // A: k col 0/8
    const int b_r  = (lane & 7) + (lane >> 4) * 8;        // B: n row within 16
    const int b_kc = ((lane >> 3) & 1) * 8;               // B: k col 0/8

    float acc[4][4][4];
    #pragma unroll
    for (int i = 0; i < 4; i++)
        #pragma unroll
        for (int j = 0; j < 4; j++)
            #pragma unroll
            for (int r = 0; r < 4; r++) acc[i][j][r] = 0.f;

    auto load_stage = [&](int c, int s) {
        const uint32_t st = sbase + s * STAGE_BYTES;
        const int k0 = c * 32;
        #pragma unroll
        for (int i = 0; i < 2; i++) {
            const int row = v0row + i * 64;
            const uint32_t d = st + row * ROWB + v0c8 * 16;
            const size_t asrc = (size_t)row * HH + k0 + v0c8 * 8;
            const size_t bsrc = (size_t)(n0 + row) * HH + k0 + v0c8 * 8;
            CP16(d,         Xh + asrc);
            CP16(d + 10240, Xl + asrc);
            CP16(d + 20480, Wh + bsrc);
            CP16(d + 30720, Wl + bsrc);
        }
        CP_COMMIT();
    };

    load_stage(0, 0);

    for (int c = 0; c < 24; c++) {
        if (c + 1 < 24) { load_stage(c + 1, (c + 1) & 1); CP_WAIT1(); }
        else            { CP_WAIT0(); }
        __syncthreads();

        const uint32_t st = sbase + (c & 1) * STAGE_BYTES;
        #pragma unroll
        for (int kh = 0; kh < 2; kh++) {
            Frag4 ah[4], al[4], bh[2], bl[2];
            #pragma unroll
            for (int mt = 0; mt < 4; mt++) {
                const uint32_t addr = st + (wm * 64 + mt * 16 + a_r) * ROWB
                                      + (kh * 16 + a_kc) * 2;
                ah[mt] = ldsm4(addr);
                al[mt] = ldsm4(addr + 10240);
            }
            #pragma unroll
            for (int np = 0; np < 2; np++) {
                const uint32_t addr = st + 20480 + (wn * 32 + np * 16 + b_r) * ROWB
                                      + (kh * 16 + b_kc) * 2;
                bh[np] = ldsm4(addr);
                bl[np] = ldsm4(addr + 10240);
            }
            #pragma unroll
            for (int mt = 0; mt < 4; mt++) {
                #pragma unroll
                for (int nt = 0; nt < 4; nt++) {
                    const int np = nt >> 1, hf = (nt & 1) * 2;
                    mma16816(acc[mt][nt], ah[mt], bh[np].r[hf], bh[np].r[hf + 1]);
                    mma16816(acc[mt][nt], ah[mt], bl[np].r[hf], bl[np].r[hf + 1]);
                    mma16816(acc[mt][nt], al[mt], bh[np].r[hf], bh[np].r[hf + 1]);
                }
            }
        }
        __syncthreads();
    }

    // epilogue: bias + store
    #pragma unroll
    for (int mt = 0; mt < 4; mt++) {
        const int row = wm * 64 + mt * 16 + (lane >> 2);
        float* yr0 = Y + ((size_t)b * SS + row) * HH;
        float* yr1 = yr0 + 8 * HH;
        #pragma unroll
        for (int nt = 0; nt < 4; nt++) {
            const int col = n0 + wn * 32 + nt * 8 + (lane & 3) * 2;
            const float bv0 = bias[col], bv1 = bias[col + 1];
            float2 o0 = make_float2(acc[mt][nt][0] + bv0, acc[mt][nt][1] + bv1);
            float2 o1 = make_float2(acc[mt][nt][2] + bv0, acc[mt][nt][3] + bv1);
            *(float2*)(yr0 + col) = o0;
            *(float2*)(yr1 + col) = o1;
        }
    }
}

// ------------------------- attention (fp32 SIMT) -------------------------
#define P_STR 132
#define ATTN_SMEM_FLOATS (128 * 64 + 64 * 128 + 128 * P_STR + 128)
#define ATTN_SMEM_BYTES  (ATTN_SMEM_FLOATS * 4)

__global__ __launch_bounds__(256)
void attn_kernel(const float* __restrict__ mask) {
    extern __shared__ float smf[];
    float* Qs = smf;
    float* Kt = smf + 128 * 64;
    float* P  = Kt + 64 * 128;
    float* em = P + 128 * P_STR;

    const int h0  = blockIdx.x;
    const int b   = blockIdx.y;
    const int tid = threadIdx.x;

    if (tid < 128) em[tid] = (1.0f - mask[b * SS + tid]) * -10000.0f;

    const size_t base = (size_t)b * SS * HH + h0 * HD;
    const float* qb = g_q + base;
    const float* kb = g_k + base;
    const float* vb = g_v + base;

    #pragma unroll
    for (int t = 0; t < 8; t++) {
        int idx = tid + t * 256;
        int row = idx >> 4;
        int c4  = (idx & 15) * 4;
        float4 q4 = *(const float4*)(qb + (size_t)row * HH + c4);
        *(float4*)&Qs[row * 64 + c4] = q4;
        float4 k4 = *(const float4*)(kb + (size_t)row * HH + c4);
        Kt[(c4 + 0) * 128 + row] = k4.x;
        Kt[(c4 + 1) * 128 + row] = k4.y;
        Kt[(c4 + 2) * 128 + row] = k4.z;
        Kt[(c4 + 3) * 128 + row] = k4.w;
    }
    __syncthreads();

    const int tx = tid & 15;
    const int ty = tid >> 4;

    float acc[8][8];
    #pragma unroll
    for (int i = 0; i < 8; i++)
        #pragma unroll
        for (int j = 0; j < 8; j++) acc[i][j] = 0.f;

    #pragma unroll 4
    for (int d = 0; d < HD; d++) {
        float q[8], kk[8];
        #pragma unroll
        for (int i = 0; i < 8; i++) q[i] = Qs[(ty * 8 + i) * 64 + d];
        #pragma unroll
        for (int j = 0; j < 8; j++) kk[j] = Kt[d * 128 + tx * 8 + j];
        #pragma unroll
        for (int i = 0; i < 8; i++)
            #pragma unroll
            for (int j = 0; j < 8; j++) acc[i][j] += q[i] * kk[j];
    }

    const float scale = 0.125f;
    #pragma unroll
    for (int i = 0; i < 8; i++) {
        int r = ty * 8 + i;
        #pragma unroll
        for (int jj = 0; jj < 8; jj += 4) {
            int c = tx * 8 + jj;
            float4 o;
            o.x = acc[i][jj + 0] * scale + em[c + 0];
            o.y = acc[i][jj + 1] * scale + em[c + 1];
            o.z = acc[i][jj + 2] * scale + em[c + 2];
            o.w = acc[i][jj + 3] * scale + em[c + 3];
            *(float4*)&P[r * P_STR + c] = o;
        }
    }
    __syncthreads();

    {
        int row = tid >> 1;
        int off = (tid & 1) * 64;
        float* pr = &P[row * P_STR + off];
        float mx = -1e30f;
        #pragma unroll 8
        for (int j = 0; j < 64; j++) mx = fmaxf(mx, pr[j]);
        mx = fmaxf(mx, __shfl_xor_sync(0xffffffffu, mx, 1));
        float sum = 0.f;
        #pragma unroll 8
        for (int j = 0; j < 64; j++) {
            float ev = __expf(pr[j] - mx);
            pr[j] = ev;
            sum += ev;
        }
        sum += __shfl_xor_sync(0xffffffffu, sum, 1);
        float inv = 1.0f / sum;
        #pragma unroll 8
        for (int j = 0; j < 64; j++) pr[j] *= inv;
    }
    __syncthreads();

    #pragma unroll
    for (int t = 0; t < 8; t++) {
        int idx = tid + t * 256;
        int row = idx >> 4;
        int c4  = (idx & 15) * 4;
        *(float4*)&Qs[row * 64 + c4] = *(const float4*)(vb + (size_t)row * HH + c4);
    }
    __syncthreads();

    float acc2[8][4] = {};
    #pragma unroll 2
    for (int t0 = 0; t0 < 128; t0 += 4) {
        float pp[8][4];
        #pragma unroll
        for (int i = 0; i < 8; i++) {
            float4 pv = *(const float4*)&P[(ty * 8 + i) * P_STR + t0];
            pp[i][0] = pv.x; pp[i][1] = pv.y; pp[i][2] = pv.z; pp[i][3] = pv.w;
        }
        #pragma unroll
        for (int u = 0; u < 4; u++) {
            float4 vv = *(const float4*)&Qs[(t0 + u) * 64 + tx * 4];
            #pragma unroll
            for (int i = 0; i < 8; i++) {
                acc2[i][0] += pp[i][u] * vv.x;
                acc2[i][1] += pp[i][u] * vv.y;
                acc2[i][2] += pp[i][u] * vv.z;
                acc2[i][3] += pp[i][u] * vv.w;
            }
        }
    }

    float* cb = g_ctx + base;
    #pragma unroll
    for (int i = 0; i < 8; i++) {
        float4 o = make_float4(acc2[i][0], acc2[i][1], acc2[i][2], acc2[i][3]);
        *(float4*)(cb + (size_t)(ty * 8 + i) * HH + tx * 4) = o;
    }
}

// ------------------------- launch -------------------------
extern "C" void kernel_launch(void* const* d_in, const int* in_sizes, int n_in,
                              void* d_out, int out_size) {
    const float* hidden  = (const float*)d_in[0];
    const float* mask    = (const float*)d_in[1];
    const float* rstates = (const float*)d_in[2];
    const float* centers = (const float*)d_in[3];
    const float* Wq = (const float*)d_in[4];
    const float* bq = (const float*)d_in[5];
    const float* Wk = (const float*)d_in[6];
    const float* bk = (const float*)d_in[7];
    const float* Wv = (const float*)d_in[8];
    const float* bv = (const float*)d_in[9];
    const float* Wo = (const float*)d_in[10];
    const float* bo = (const float*)d_in[11];
    float* out = (float*)d_out;

    static bool init_done = false;
    static void *pq, *pk, *pv, *pc, *pxh, *pxl, *pwh, *pwl;
    if (!init_done) {
        cudaGetSymbolAddress(&pq,  g_q);
        cudaGetSymbolAddress(&pk,  g_k);
        cudaGetSymbolAddress(&pv,  g_v);
        cudaGetSymbolAddress(&pc,  g_ctx);
        cudaGetSymbolAddress(&pxh, g_xhi);
        cudaGetSymbolAddress(&pxl, g_xlo);
        cudaGetSymbolAddress(&pwh, g_whi);
        cudaGetSymbolAddress(&pwl, g_wlo);
        cudaFuncSetAttribute(attn_kernel, cudaFuncAttributeMaxDynamicSharedMemorySize,
                             ATTN_SMEM_BYTES);
        cudaFuncSetAttribute(gemm_mma, cudaFuncAttributeMaxDynamicSharedMemorySize,
                             GEMM_SMEM);
        init_done = true;
    }

    bf16* xhi = (bf16*)pxh;
    bf16* xlo = (bf16*)pxl;
    bf16* whi = (bf16*)pwh;
    bf16* wlo = (bf16*)pwl;
    const size_t WSTR = (size_t)2 * HH * HH;

    routing_kernel<<<BB, 256>>>(rstates, centers);

    const int n4 = BB * SS * HH / 4;
    conv_act<<<4096, 256>>>(hidden, xhi, xlo, n4);

    dim3 wg(HH / 32, HH / 32, 2);
    conv_w<<<wg, dim3(32, 8)>>>(Wq, whi + 0 * WSTR, wlo + 0 * WSTR);
    conv_w<<<wg, dim3(32, 8)>>>(Wk, whi + 1 * WSTR, wlo + 1 * WSTR);
    conv_w<<<wg, dim3(32, 8)>>>(Wv, whi + 2 * WSTR, wlo + 2 * WSTR);
    conv_w<<<wg, dim3(32, 8)>>>(Wo, whi + 3 * WSTR, wlo + 3 * WSTR);

    // fused QKV: grid z in {0,1,2} selects weights (z*WSTR), bias, output
    gemm_mma<<<dim3(HH / 128, BB, 3), 256, GEMM_SMEM>>>(
        xhi, xlo, whi, wlo, bq, bk, bv, (float*)pq, (float*)pk, (float*)pv);

    attn_kernel<<<dim3(NH, BB), 256, ATTN_SMEM_BYTES>>>(mask);

    conv_act<<<4096, 256>>>((const float*)pc, xhi, xlo, n4);
    // O: single mat -> pass its weights as base, z extent 1
    gemm_mma<<<dim3(HH / 128, BB, 1), 256, GEMM_SMEM>>>(
        xhi, xlo, whi + 3 * WSTR, wlo + 3 * WSTR, bo, bo, bo, out, out, out);
}

// round 6
// speedup vs baseline: 2.9478x; 1.0277x over previous
#include <cuda_runtime.h>
#include <cuda_bf16.h>
#include <cstdint>

// ExpertAttention: B=128, S=128, H=768, E=2, 12 heads x 64
// R6: mma.sync bf16 GEMMs (3-term split) + f32x2 attention + fused conversions.
// Launch order puts gemm_mma (O) 6th so ncu -s5 -c1 profiles it.

#define BB   128
#define SS   128
#define HH   768
#define NH   12
#define HD   64

typedef __nv_bfloat16 bf16;
typedef unsigned long long u64;

// ------------------------- scratch (static device mem) -------------------------
__device__ int   g_assign[BB];
__device__ __align__(16) float g_q[(size_t)BB * SS * HH];
__device__ __align__(16) float g_k[(size_t)BB * SS * HH];
__device__ __align__(16) float g_v[(size_t)BB * SS * HH];
__device__ __align__(16) bf16  g_xhi[(size_t)BB * SS * HH];
__device__ __align__(16) bf16  g_xlo[(size_t)BB * SS * HH];
// transposed weights [mat][e][n][h], mat in {q,k,v,o}
__device__ __align__(16) bf16  g_whi[(size_t)4 * 2 * HH * HH];
__device__ __align__(16) bf16  g_wlo[(size_t)4 * 2 * HH * HH];

// ------------------------- helpers -------------------------
__device__ __forceinline__ uint32_t smem_u32(const void* p) {
    uint32_t a;
    asm("{ .reg .u64 t; cvta.to.shared.u64 t, %1; cvt.u32.u64 %0, t; }" : "=r"(a) : "l"(p));
    return a;
}

__device__ __forceinline__ u64 pack2(float lo, float hi) {
    u64 r;
    asm("mov.b64 %0, {%1, %2};" : "=l"(r) : "f"(lo), "f"(hi));
    return r;
}
__device__ __forceinline__ u64 fma2(u64 a, u64 b, u64 c) {
    u64 d;
    asm("fma.rn.f32x2 %0, %1, %2, %3;" : "=l"(d) : "l"(a), "l"(b), "l"(c));
    return d;
}
__device__ __forceinline__ void unpack2(u64 v, float& lo, float& hi) {
    asm("mov.b64 {%0, %1}, %2;" : "=f"(lo), "=f"(hi) : "l"(v));
}

#define CP16(dst, src) \
    asm volatile("cp.async.cg.shared.global [%0], [%1], 16;" :: "r"(dst), "l"(src))
#define CP_COMMIT() asm volatile("cp.async.commit_group;" ::: "memory")
#define CP_WAIT1()  asm volatile("cp.async.wait_group 1;" ::: "memory")
#define CP_WAIT0()  asm volatile("cp.async.wait_group 0;" ::: "memory")

struct Frag4 { uint32_t r[4]; };

__device__ __forceinline__ Frag4 ldsm4(uint32_t addr) {
    Frag4 f;
    asm volatile("ldmatrix.sync.aligned.m8n8.x4.shared.b16 {%0,%1,%2,%3}, [%4];"
                 : "=r"(f.r[0]), "=r"(f.r[1]), "=r"(f.r[2]), "=r"(f.r[3]) : "r"(addr));
    return f;
}

__device__ __forceinline__ void mma16816(float* d, const Frag4& a, uint32_t b0, uint32_t b1) {
    asm volatile(
        "mma.sync.aligned.m16n8k16.row.col.f32.bf16.bf16.f32 "
        "{%0,%1,%2,%3}, {%4,%5,%6,%7}, {%8,%9}, {%0,%1,%2,%3};"
        : "+f"(d[0]), "+f"(d[1]), "+f"(d[2]), "+f"(d[3])
        : "r"(a.r[0]), "r"(a.r[1]), "r"(a.r[2]), "r"(a.r[3]), "r"(b0), "r"(b1));
}

// ------------------------- routing -------------------------
__global__ void routing_kernel(const float* __restrict__ rs,
                               const float* __restrict__ centers) {
    const int b   = blockIdx.x;
    const int tid = threadIdx.x;  // 256

    float d0 = 0.f, d1 = 0.f;
    for (int h = tid; h < HH; h += 256) {
        const float* p = rs + (size_t)b * SS * HH + h;
        float s = 0.f;
        #pragma unroll 8
        for (int t = 0; t < SS; t++) s += p[(size_t)t * HH];
        float m  = s * (1.0f / 128.0f);
        float e0 = m - centers[h];
        float e1 = m - centers[HH + h];
        d0 += e0 * e0;
        d1 += e1 * e1;
    }
    __shared__ float s0[256], s1[256];
    s0[tid] = d0; s1[tid] = d1;
    __syncthreads();
    for (int w = 128; w > 0; w >>= 1) {
        if (tid < w) { s0[tid] += s0[tid + w]; s1[tid] += s1[tid + w]; }
        __syncthreads();
    }
    if (tid == 0) g_assign[b] = (s1[0] < s0[0]) ? 1 : 0;
}

// ------------------------- conversions -------------------------
__global__ void conv_act(const float* __restrict__ x, bf16* __restrict__ hi,
                         bf16* __restrict__ lo, int n4) {
    int i = blockIdx.x * blockDim.x + threadIdx.x;
    int stride = gridDim.x * blockDim.x;
    for (; i < n4; i += stride) {
        float4 v = ((const float4*)x)[i];
        bf16 h0 = __float2bfloat16(v.x);
        bf16 h1 = __float2bfloat16(v.y);
        bf16 h2 = __float2bfloat16(v.z);
        bf16 h3 = __float2bfloat16(v.w);
        bf16 l0 = __float2bfloat16(v.x - __bfloat162float(h0));
        bf16 l1 = __float2bfloat16(v.y - __bfloat162float(h1));
        bf16 l2 = __float2bfloat16(v.z - __bfloat162float(h2));
        bf16 l3 = __float2bfloat16(v.w - __bfloat162float(h3));
        __nv_bfloat162* ph = (__nv_bfloat162*)hi;
        __nv_bfloat162* pl = (__nv_bfloat162*)lo;
        ph[2 * i]     = __nv_bfloat162(h0, h1);
        ph[2 * i + 1] = __nv_bfloat162(h2, h3);
        pl[2 * i]     = __nv_bfloat162(l0, l1);
        pl[2 * i + 1] = __nv_bfloat162(l2, l3);
    }
}

// All 4 W mats in one launch. z = mat*2+e. W[e][h][n] -> hi/lo[mat][e][n][h].
__global__ void conv_w_all(const float* __restrict__ W0, const float* __restrict__ W1,
                           const float* __restrict__ W2, const float* __restrict__ W3,
                           bf16* __restrict__ hi, bf16* __restrict__ lo) {
    __shared__ float t[32][33];
    const int z   = blockIdx.z;
    const int mat = z >> 1, e = z & 1;
    const float* W = (mat == 0) ? W0 : (mat == 1) ? W1 : (mat == 2) ? W2 : W3;
    const float* Wp = W + (size_t)e * HH * HH;
    const int h0 = blockIdx.x * 32, n0 = blockIdx.y * 32;
    for (int r = threadIdx.y; r < 32; r += 8)
        t[r][threadIdx.x] = Wp[(size_t)(h0 + r) * HH + n0 + threadIdx.x];
    __syncthreads();
    const size_t ob = ((size_t)mat * 2 + e) * HH * HH;
    for (int r = threadIdx.y; r < 32; r += 8) {
        float v = t[threadIdx.x][r];  // = W[h0+tx][n0+r]
        bf16 h = __float2bfloat16(v);
        bf16 l = __float2bfloat16(v - __bfloat162float(h));
        size_t o = ob + (size_t)(n0 + r) * HH + h0 + threadIdx.x;
        hi[o] = h;
        lo[o] = l;
    }
}

// ------------------------- mma.sync GEMM -------------------------
// Y[b,s,n] = sum_h X[b,s,h]*W[e,h,n] + bias[e,n], bf16 3-term split.
// Block 128x128x32, 256 thr / 8 warps (2m x 4n), warp tile 64x32.
// SMEM stage (40960B): Ahi@0, Alo@10240, Bhi@20480, Blo@30720; ROWB=80.
#define STAGE_BYTES 40960
#define GEMM_SMEM   (2 * STAGE_BYTES)
#define ROWB        80

__global__ __launch_bounds__(256, 2)
void gemm_mma(const bf16* __restrict__ Xhi, const bf16* __restrict__ Xlo,
              const bf16* __restrict__ Whi, const bf16* __restrict__ Wlo,
              const float* __restrict__ bq, const float* __restrict__ bk,
              const float* __restrict__ bv,
              float* __restrict__ Y0, float* __restrict__ Y1, float* __restrict__ Y2) {
    extern __shared__ char smem[];
    const int tid  = threadIdx.x;
    const int lane = tid & 31;
    const int wid  = tid >> 5;
    const int wm   = wid & 1;
    const int wn   = wid >> 1;

    const int n0  = blockIdx.x * 128;
    const int b   = blockIdx.y;
    const int mat = blockIdx.z;
    const int e   = g_assign[b];

    const float* __restrict__ bias = ((mat == 0) ? bq : (mat == 1) ? bk : bv) + e * HH;
    float* __restrict__ Y = (mat == 0) ? Y0 : (mat == 1) ? Y1 : Y2;

    const size_t woff = ((size_t)mat * 2 + e) * HH * HH;
    const bf16* __restrict__ Xh = Xhi + (size_t)b * SS * HH;
    const bf16* __restrict__ Xl = Xlo + (size_t)b * SS * HH;
    const bf16* __restrict__ Wh = Whi + woff;
    const bf16* __restrict__ Wl = Wlo + woff;

    const uint32_t sbase = smem_u32(smem);

    const int v0row = tid >> 2;
    const int v0c8  = tid & 3;

    const int a_r  = (lane & 7) + ((lane >> 3) & 1) * 8;
    const int a_kc = (lane >> 4) * 8;
    const int b_r  = (lane & 7) + (lane >> 4) * 8;
    const int b_kc = ((lane >> 3) & 1) * 8;

    float acc[4][4][4];
    #pragma unroll
    for (int i = 0; i < 4; i++)
        #pragma unroll
        for (int j = 0; j < 4; j++)
            #pragma unroll
            for (int r = 0; r < 4; r++) acc[i][j][r] = 0.f;

    auto load_stage = [&](int c, int s) {
        const uint32_t st = sbase + s * STAGE_BYTES;
        const int k0 = c * 32;
        #pragma unroll
        for (int i = 0; i < 2; i++) {
            const int row = v0row + i * 64;
            const uint32_t d = st + row * ROWB + v0c8 * 16;
            const size_t asrc = (size_t)row * HH + k0 + v0c8 * 8;
            const size_t bsrc = (size_t)(n0 + row) * HH + k0 + v0c8 * 8;
            CP16(d,         Xh + asrc);
            CP16(d + 10240, Xl + asrc);
            CP16(d + 20480, Wh + bsrc);
            CP16(d + 30720, Wl + bsrc);
        }
        CP_COMMIT();
    };

    load_stage(0, 0);

    for (int c = 0; c < 24; c++) {
        if (c + 1 < 24) { load_stage(c + 1, (c + 1) & 1); CP_WAIT1(); }
        else            { CP_WAIT0(); }
        __syncthreads();

        const uint32_t st = sbase + (c & 1) * STAGE_BYTES;
        #pragma unroll
        for (int kh = 0; kh < 2; kh++) {
            Frag4 ah[4], al[4], bh[2], bl[2];
            #pragma unroll
            for (int mt = 0; mt < 4; mt++) {
                const uint32_t addr = st + (wm * 64 + mt * 16 + a_r) * ROWB
                                      + (kh * 16 + a_kc) * 2;
                ah[mt] = ldsm4(addr);
                al[mt] = ldsm4(addr + 10240);
            }
            #pragma unroll
            for (int np = 0; np < 2; np++) {
                const uint32_t addr = st + 20480 + (wn * 32 + np * 16 + b_r) * ROWB
                                      + (kh * 16 + b_kc) * 2;
                bh[np] = ldsm4(addr);
                bl[np] = ldsm4(addr + 10240);
            }
            #pragma unroll
            for (int mt = 0; mt < 4; mt++) {
                #pragma unroll
                for (int nt = 0; nt < 4; nt++) {
                    const int np = nt >> 1, hf = (nt & 1) * 2;
                    mma16816(acc[mt][nt], ah[mt], bh[np].r[hf], bh[np].r[hf + 1]);
                    mma16816(acc[mt][nt], ah[mt], bl[np].r[hf], bl[np].r[hf + 1]);
                    mma16816(acc[mt][nt], al[mt], bh[np].r[hf], bh[np].r[hf + 1]);
                }
            }
        }
        __syncthreads();
    }

    #pragma unroll
    for (int mt = 0; mt < 4; mt++) {
        const int row = wm * 64 + mt * 16 + (lane >> 2);
        float* yr0 = Y + ((size_t)b * SS + row) * HH;
        float* yr1 = yr0 + 8 * HH;
        #pragma unroll
        for (int nt = 0; nt < 4; nt++) {
            const int col = n0 + wn * 32 + nt * 8 + (lane & 3) * 2;
            const float bv0 = bias[col], bv1 = bias[col + 1];
            float2 o0 = make_float2(acc[mt][nt][0] + bv0, acc[mt][nt][1] + bv1);
            float2 o1 = make_float2(acc[mt][nt][2] + bv0, acc[mt][nt][3] + bv1);
            *(float2*)(yr0 + col) = o0;
            *(float2*)(yr1 + col) = o1;
        }
    }
}

// ------------------------- attention (f32x2 SIMT, bf16 split epilogue) ---------
#define P_STR 132
#define ATTN_SMEM_FLOATS (128 * 64 + 64 * 128 + 128 * P_STR + 128)
#define ATTN_SMEM_BYTES  (ATTN_SMEM_FLOATS * 4)

__global__ __launch_bounds__(256)
void attn_kernel(const float* __restrict__ mask,
                 bf16* __restrict__ chi, bf16* __restrict__ clo) {
    extern __shared__ float smf[];
    float* Qs = smf;                   // [128][64], later V
    float* Kt = smf + 128 * 64;        // [64][128]
    float* P  = Kt + 64 * 128;         // [128][P_STR]
    float* em = P + 128 * P_STR;       // [128]

    const int h0  = blockIdx.x;
    const int b   = blockIdx.y;
    const int tid = threadIdx.x;

    if (tid < 128) em[tid] = (1.0f - mask[b * SS + tid]) * -10000.0f;

    const size_t base = (size_t)b * SS * HH + h0 * HD;
    const float* qb = g_q + base;
    const float* kb = g_k + base;
    const float* vb = g_v + base;

    #pragma unroll
    for (int t = 0; t < 8; t++) {
        int idx = tid + t * 256;
        int row = idx >> 4;
        int c4  = (idx & 15) * 4;
        float4 q4 = *(const float4*)(qb + (size_t)row * HH + c4);
        *(float4*)&Qs[row * 64 + c4] = q4;
        float4 k4 = *(const float4*)(kb + (size_t)row * HH + c4);
        Kt[(c4 + 0) * 128 + row] = k4.x;
        Kt[(c4 + 1) * 128 + row] = k4.y;
        Kt[(c4 + 2) * 128 + row] = k4.z;
        Kt[(c4 + 3) * 128 + row] = k4.w;
    }
    __syncthreads();

    const int tx = tid & 15;   // key cols tx*8..+7
    const int ty = tid >> 4;   // query rows ty*8..+7

    // scores S = Q K^T, f32x2 packed over key-col pairs
    u64 acc[8][4];
    #pragma unroll
    for (int i = 0; i < 8; i++)
        #pragma unroll
        for (int u = 0; u < 4; u++) acc[i][u] = 0ull;

    #pragma unroll 4
    for (int d = 0; d < HD; d++) {
        u64 kk[4];
        #pragma unroll
        for (int u = 0; u < 4; u++)
            kk[u] = *(const u64*)&Kt[d * 128 + tx * 8 + u * 2];
        #pragma unroll
        for (int i = 0; i < 8; i++) {
            float qv = Qs[(ty * 8 + i) * 64 + d];
            u64 qq = pack2(qv, qv);
            #pragma unroll
            for (int u = 0; u < 4; u++) acc[i][u] = fma2(qq, kk[u], acc[i][u]);
        }
    }

    const float scale = 0.125f;  // 1/sqrt(64)
    #pragma unroll
    for (int i = 0; i < 8; i++) {
        int r = ty * 8 + i;
        #pragma unroll
        for (int u = 0; u < 4; u++) {
            int c = tx * 8 + u * 2;
            float s0, s1;
            unpack2(acc[i][u], s0, s1);
            float2 o = make_float2(s0 * scale + em[c], s1 * scale + em[c + 1]);
            *(float2*)&P[r * P_STR + c] = o;
        }
    }
    __syncthreads();

    // softmax: 2 threads per row
    {
        int row = tid >> 1;
        int off = (tid & 1) * 64;
        float* pr = &P[row * P_STR + off];
        float mx = -1e30f;
        #pragma unroll 8
        for (int j = 0; j < 64; j++) mx = fmaxf(mx, pr[j]);
        mx = fmaxf(mx, __shfl_xor_sync(0xffffffffu, mx, 1));
        float sum = 0.f;
        #pragma unroll 8
        for (int j = 0; j < 64; j++) {
            float ev = __expf(pr[j] - mx);
            pr[j] = ev;
            sum += ev;
        }
        sum += __shfl_xor_sync(0xffffffffu, sum, 1);
        float inv = 1.0f / sum;
        #pragma unroll 8
        for (int j = 0; j < 64; j++) pr[j] *= inv;
    }
    __syncthreads();

    // load V into Qs buffer
    #pragma unroll
    for (int t = 0; t < 8; t++) {
        int idx = tid + t * 256;
        int row = idx >> 4;
        int c4  = (idx & 15) * 4;
        *(float4*)&Qs[row * 64 + c4] = *(const float4*)(vb + (size_t)row * HH + c4);
    }
    __syncthreads();

    // ctx = P @ V, f32x2 packed over output-col pairs
    u64 acc2[8][2];
    #pragma unroll
    for (int i = 0; i < 8; i++) { acc2[i][0] = 0ull; acc2[i][1] = 0ull; }

    #pragma unroll 2
    for (int t0 = 0; t0 < 128; t0 += 4) {
        float pp[8][4];
        #pragma unroll
        for (int i = 0; i < 8; i++) {
            float4 pv = *(const float4*)&P[(ty * 8 + i) * P_STR + t0];
            pp[i][0] = pv.x; pp[i][1] = pv.y; pp[i][2] = pv.z; pp[i][3] = pv.w;
        }
        #pragma unroll
        for (int u = 0; u < 4; u++) {
            u64 v01 = *(const u64*)&Qs[(t0 + u) * 64 + tx * 4];
            u64 v23 = *(const u64*)&Qs[(t0 + u) * 64 + tx * 4 + 2];
            #pragma unroll
            for (int i = 0; i < 8; i++) {
                u64 pu = pack2(pp[i][u], pp[i][u]);
                acc2[i][0] = fma2(pu, v01, acc2[i][0]);
                acc2[i][1] = fma2(pu, v23, acc2[i][1]);
            }
        }
    }

    // epilogue: split ctx to bf16 hi/lo directly (feeds O-projection GEMM)
    bf16* ch = chi + base;
    bf16* cl = clo + base;
    #pragma unroll
    for (int i = 0; i < 8; i++) {
        float c0, c1, c2, c3;
        unpack2(acc2[i][0], c0, c1);
        unpack2(acc2[i][1], c2, c3);
        bf16 h0 = __float2bfloat16(c0);
        bf16 h1 = __float2bfloat16(c1);
        bf16 h2 = __float2bfloat16(c2);
        bf16 h3 = __float2bfloat16(c3);
        bf16 l0 = __float2bfloat16(c0 - __bfloat162float(h0));
        bf16 l1 = __float2bfloat16(c1 - __bfloat162float(h1));
        bf16 l2 = __float2bfloat16(c2 - __bfloat162float(h2));
        bf16 l3 = __float2bfloat16(c3 - __bfloat162float(h3));
        const size_t o = (size_t)(ty * 8 + i) * HH + tx * 4;
        __nv_bfloat162 hh0(h0, h1), hh1(h2, h3), ll0(l0, l1), ll1(l2, l3);
        *(uint2*)(ch + o) = make_uint2(*(uint32_t*)&hh0, *(uint32_t*)&hh1);
        *(uint2*)(cl + o) = make_uint2(*(uint32_t*)&ll0, *(uint32_t*)&ll1);
    }
}

// ------------------------- launch -------------------------
extern "C" void kernel_launch(void* const* d_in, const int* in_sizes, int n_in,
                              void* d_out, int out_size) {
    const float* hidden  = (const float*)d_in[0];
    const float* mask    = (const float*)d_in[1];
    const float* rstates = (const float*)d_in[2];
    const float* centers = (const float*)d_in[3];
    const float* Wq = (const float*)d_in[4];
    const float* bq = (const float*)d_in[5];
    const float* Wk = (const float*)d_in[6];
    const float* bk = (const float*)d_in[7];
    const float* Wv = (const float*)d_in[8];
    const float* bv = (const float*)d_in[9];
    const float* Wo = (const float*)d_in[10];
    const float* bo = (const float*)d_in[11];
    float* out = (float*)d_out;

    static bool init_done = false;
    static void *pq, *pk, *pv, *pxh, *pxl, *pwh, *pwl;
    if (!init_done) {
        cudaGetSymbolAddress(&pq,  g_q);
        cudaGetSymbolAddress(&pk,  g_k);
        cudaGetSymbolAddress(&pv,  g_v);
        cudaGetSymbolAddress(&pxh, g_xhi);
        cudaGetSymbolAddress(&pxl, g_xlo);
        cudaGetSymbolAddress(&pwh, g_whi);
        cudaGetSymbolAddress(&pwl, g_wlo);
        cudaFuncSetAttribute(attn_kernel, cudaFuncAttributeMaxDynamicSharedMemorySize,
                             ATTN_SMEM_BYTES);
        cudaFuncSetAttribute(gemm_mma, cudaFuncAttributeMaxDynamicSharedMemorySize,
                             GEMM_SMEM);
        init_done = true;
    }

    bf16* xhi = (bf16*)pxh;
    bf16* xlo = (bf16*)pxl;
    bf16* whi = (bf16*)pwh;
    bf16* wlo = (bf16*)pwl;
    const size_t WSTR = (size_t)2 * HH * HH;

    // launch 1
    routing_kernel<<<BB, 256>>>(rstates, centers);
    // launch 2
    const int n4 = BB * SS * HH / 4;
    conv_act<<<4096, 256>>>(hidden, xhi, xlo, n4);
    // launch 3: all 4 weight mats, z = mat*2+e
    conv_w_all<<<dim3(HH / 32, HH / 32, 8), dim3(32, 8)>>>(Wq, Wk, Wv, Wo, whi, wlo);
    // launch 4: fused QKV (z in {0,1,2})
    gemm_mma<<<dim3(HH / 128, BB, 3), 256, GEMM_SMEM>>>(
        xhi, xlo, whi, wlo, bq, bk, bv, (float*)pq, (float*)pk, (float*)pv);
    // launch 5: attention (writes ctx as bf16 hi/lo into xhi/xlo)
    attn_kernel<<<dim3(NH, BB), 256, ATTN_SMEM_BYTES>>>(mask, xhi, xlo);
    // launch 6: O projection (profiled by ncu -s5 -c1)
    gemm_mma<<<dim3(HH / 128, BB, 1), 256, GEMM_SMEM>>>(
        xhi, xlo, whi + 3 * WSTR, wlo + 3 * WSTR, bo, bo, bo, out, out, out);
}